// round 11
// baseline (speedup 1.0000x reference)
#include <cuda_runtime.h>
#include <cuda_bf16.h>
#include <math.h>
#include <stdint.h>

#define D 128
#define MAXN 50000

// ---------------- scratch ----------------
__device__ float g_h[MAXN * D];
__device__ float g_agg[MAXN * D];          // scatter-add of h over edges
__device__ float g_gi[MAXN * 3 * D];
__device__ float g_gh[MAXN * 3 * D];
__device__ float g_wihT[D * 3 * D];        // [K=128][M=384]
__device__ float g_whhT[D * 3 * D];
__device__ float g_wcomb[2 * D * 3 * D];   // conv_w[l] @ w_ihT : [128][384] per layer

// ---------------- weight transpose: WT[k][m] = W[m][k], W is [384,128] ----------------
__global__ void transpose_kernel(const float* __restrict__ W, float* __restrict__ WT) {
    int idx = blockIdx.x * blockDim.x + threadIdx.x;
    if (idx >= 3 * D * D) return;
    int m = idx / D;
    int k = idx % D;
    WT[(size_t)k * (3 * D) + m] = W[idx];
}

// ---------------- FFMA register-blocked GEMM, BK=32 ----------------
// C[N x M] = A[N x 128] @ B[128 x M]; M multiple of 128.
// Tile 128x128, 256 threads, 8x8 outputs/thread (2x2 chunks of 4, split 64).
#define BK 32
__global__ __launch_bounds__(256, 2)
void gemm128(const float* __restrict__ A, const float* __restrict__ B,
             float* __restrict__ C, int N, int M) {
    __shared__ float As[BK][132];   // transposed As[k][m]
    __shared__ float Bs[BK][128];   // Bs[k][n]

    int tid = threadIdx.x;
    int block_row = blockIdx.y * 128;
    int block_col = blockIdx.x * 128;

    int aRow = tid >> 2;            // 0..63 (2 passes -> 128 rows)
    int aCol = (tid & 3) * 8;       // 0,8,16,24 (two float4 each)
    int bRow = tid >> 5;            // 0..7 (4 passes -> 32 rows)
    int bCol = (tid & 31) * 4;
    int tr = (tid >> 4) * 4;
    int tc = (tid & 15) * 4;

    float acc[8][8];
#pragma unroll
    for (int i = 0; i < 8; i++)
#pragma unroll
        for (int j = 0; j < 8; j++) acc[i][j] = 0.0f;

    for (int k0 = 0; k0 < 128; k0 += BK) {
#pragma unroll
        for (int p = 0; p < 2; p++) {
            int r = aRow + p * 64;
            int gr = block_row + r;
            float4 v0 = make_float4(0.f, 0.f, 0.f, 0.f);
            float4 v1 = v0;
            if (gr < N) {
                const float* ap = A + (size_t)gr * 128 + k0 + aCol;
                v0 = *(const float4*)ap;
                v1 = *(const float4*)(ap + 4);
            }
            As[aCol + 0][r] = v0.x;
            As[aCol + 1][r] = v0.y;
            As[aCol + 2][r] = v0.z;
            As[aCol + 3][r] = v0.w;
            As[aCol + 4][r] = v1.x;
            As[aCol + 5][r] = v1.y;
            As[aCol + 6][r] = v1.z;
            As[aCol + 7][r] = v1.w;
        }
#pragma unroll
        for (int p = 0; p < 4; p++) {
            int r = bRow + p * 8;
            float4 v = *(const float4*)(B + (size_t)(k0 + r) * M + block_col + bCol);
            *(float4*)&Bs[r][bCol] = v;
        }
        __syncthreads();

#pragma unroll
        for (int k = 0; k < BK; k++) {
            float4 m0 = *(const float4*)&As[k][tr];
            float4 m1 = *(const float4*)&As[k][tr + 64];
            float4 n0 = *(const float4*)&Bs[k][tc];
            float4 n1 = *(const float4*)&Bs[k][tc + 64];
            float rm[8] = {m0.x, m0.y, m0.z, m0.w, m1.x, m1.y, m1.z, m1.w};
            float rn[8] = {n0.x, n0.y, n0.z, n0.w, n1.x, n1.y, n1.z, n1.w};
#pragma unroll
            for (int i = 0; i < 8; i++)
#pragma unroll
                for (int j = 0; j < 8; j++)
                    acc[i][j] = fmaf(rm[i], rn[j], acc[i][j]);
        }
        __syncthreads();
    }

#pragma unroll
    for (int ii = 0; ii < 2; ii++) {
#pragma unroll
        for (int i = 0; i < 4; i++) {
            int row = block_row + tr + ii * 64 + i;
            if (row >= N) continue;
#pragma unroll
            for (int jj = 0; jj < 2; jj++) {
                int col = block_col + tc + jj * 64;
                float4 r;
                r.x = acc[ii * 4 + i][jj * 4 + 0];
                r.y = acc[ii * 4 + i][jj * 4 + 1];
                r.z = acc[ii * 4 + i][jj * 4 + 2];
                r.w = acc[ii * 4 + i][jj * 4 + 3];
                *(float4*)&C[(size_t)row * M + col] = r;
            }
        }
    }
}

// ---------------- gather: h = embed[node_ids]; also zero agg ----------------
__global__ void gather_kernel(const int* __restrict__ node_ids,
                              const float4* __restrict__ embed4,
                              float4* __restrict__ h4,
                              float4* __restrict__ agg4, int N) {
    int idx = blockIdx.x * blockDim.x + threadIdx.x;
    if (idx >= N * 32) return;
    int n = idx >> 5;
    int c = idx & 31;
    int id = node_ids[n];
    h4[(size_t)n * 32 + c] = embed4[(size_t)id * 32 + c];
    agg4[idx] = make_float4(0.f, 0.f, 0.f, 0.f);
}

// ---------------- persistent edge scatter: agg[dst] += h[src], grid-stride, ILP-4 ----------------
#define RED4(P, V)                                                         \
    asm volatile("red.global.add.v4.f32 [%0], {%1, %2, %3, %4};"           \
                 :: "l"(P), "f"((V).x), "f"((V).y), "f"((V).z), "f"((V).w) \
                 : "memory")

__global__ void scatter_kernel(const float4* __restrict__ h4,
                               const int* __restrict__ src,
                               const int* __restrict__ dst,
                               float* __restrict__ agg, int E) {
    int warpsTotal = gridDim.x * (blockDim.x >> 5);
    int w = blockIdx.x * (blockDim.x >> 5) + (threadIdx.x >> 5);
    int lane = threadIdx.x & 31;
    for (int e0 = w * 4; e0 < E; e0 += warpsTotal * 4) {
        if (e0 + 4 <= E) {
            int s0 = __ldg(src + e0 + 0), s1 = __ldg(src + e0 + 1);
            int s2 = __ldg(src + e0 + 2), s3 = __ldg(src + e0 + 3);
            int d0 = __ldg(dst + e0 + 0), d1 = __ldg(dst + e0 + 1);
            int d2 = __ldg(dst + e0 + 2), d3 = __ldg(dst + e0 + 3);
            float4 v0 = h4[(size_t)s0 * 32 + lane];
            float4 v1 = h4[(size_t)s1 * 32 + lane];
            float4 v2 = h4[(size_t)s2 * 32 + lane];
            float4 v3 = h4[(size_t)s3 * 32 + lane];
            RED4(agg + (size_t)d0 * D + lane * 4, v0);
            RED4(agg + (size_t)d1 * D + lane * 4, v1);
            RED4(agg + (size_t)d2 * D + lane * 4, v2);
            RED4(agg + (size_t)d3 * D + lane * 4, v3);
        } else {
            for (int e = e0; e < E; e++) {
                int s = __ldg(src + e);
                int d = __ldg(dst + e);
                float4 v = h4[(size_t)s * 32 + lane];
                RED4(agg + (size_t)d * D + lane * 4, v);
            }
        }
    }
}

// ---------------- GRU gate fusion (biases folded); optionally zero agg ----------------
__global__ void gru_kernel(const float4* __restrict__ gi4,
                           const float4* __restrict__ gh4,
                           const float4* __restrict__ bih4,
                           const float4* __restrict__ bhh4,
                           float4* __restrict__ h4,
                           float4* __restrict__ agg4,
                           int total4, int zero_agg) {
    int idx = blockIdx.x * blockDim.x + threadIdx.x;
    if (idx >= total4) return;
    int n = idx >> 5;
    int c = idx & 31;
    const float4* gin = gi4 + (size_t)n * 96;
    const float4* ghn = gh4 + (size_t)n * 96;
    float4 ir = gin[c], iz = gin[c + 32], in_ = gin[c + 64];
    float4 hr = ghn[c], hz = ghn[c + 32], hn = ghn[c + 64];
    float4 bir = bih4[c], biz = bih4[c + 32], bin = bih4[c + 64];
    float4 bhr = bhh4[c], bhz = bhh4[c + 32], bhn = bhh4[c + 64];
    float4 h = h4[idx];
    float4 o;
#define GRU1(X)                                                                 \
    {                                                                           \
        float r = 1.0f / (1.0f + __expf(-(ir.X + bir.X + hr.X + bhr.X)));       \
        float z = 1.0f / (1.0f + __expf(-(iz.X + biz.X + hz.X + bhz.X)));       \
        float nn = tanhf(in_.X + bin.X + r * (hn.X + bhn.X));                   \
        o.X = (1.0f - z) * nn + z * h.X;                                        \
    }
    GRU1(x) GRU1(y) GRU1(z) GRU1(w)
#undef GRU1
    h4[idx] = o;
    if (zero_agg) agg4[idx] = make_float4(0.f, 0.f, 0.f, 0.f);
}

// ---------------- per-graph mean pool (batch sorted) ----------------
__device__ __forceinline__ int lower_bound_dev(const int* a, int n, int key) {
    int lo = 0, hi = n;
    while (lo < hi) {
        int mid = (lo + hi) >> 1;
        if (a[mid] < key) lo = mid + 1; else hi = mid;
    }
    return lo;
}

__global__ void pool_kernel(const float* __restrict__ h,
                            const int* __restrict__ batch,
                            float* __restrict__ out, int N) {
    int g = blockIdx.x;
    int tid = threadIdx.x;
    int sub = tid >> 7;
    int d = tid & 127;
    __shared__ int s_lo, s_hi;
    __shared__ float sbuf[4][128];
    if (tid == 0) {
        s_lo = lower_bound_dev(batch, N, g);
        s_hi = lower_bound_dev(batch, N, g + 1);
    }
    __syncthreads();
    int lo = s_lo, hi = s_hi;
    float acc = 0.0f;
    for (int n = lo + sub; n < hi; n += 4)
        acc += h[(size_t)n * D + d];
    sbuf[sub][d] = acc;
    __syncthreads();
    if (sub == 0) {
        float total = sbuf[0][d] + sbuf[1][d] + sbuf[2][d] + sbuf[3][d];
        float cnt = (float)(hi - lo);
        out[(size_t)g * D + d] = total / fmaxf(cnt, 1.0f);
    }
}

// ---------------- launch ----------------
extern "C" void kernel_launch(void* const* d_in, const int* in_sizes, int n_in,
                              void* d_out, int out_size) {
    const int* node_ids = (const int*)d_in[0];
    const int* edge_index = (const int*)d_in[1];
    const int* batch = (const int*)d_in[2];
    const float* embed = (const float*)d_in[4];
    const float* conv_w = (const float*)d_in[5];   // [2][K=128][M=128]
    const float* w_ih = (const float*)d_in[6];
    const float* w_hh = (const float*)d_in[7];
    const float* b_ih = (const float*)d_in[8];
    const float* b_hh = (const float*)d_in[9];
    float* out = (float*)d_out;

    int N = in_sizes[0];
    int E = in_sizes[1] / 2;
    int G = out_size / D;
    const int* src = edge_index;
    const int* dst = edge_index + E;

    float *h, *agg, *gi, *gh, *wihT, *whhT, *wcomb;
    cudaGetSymbolAddress((void**)&h, g_h);
    cudaGetSymbolAddress((void**)&agg, g_agg);
    cudaGetSymbolAddress((void**)&gi, g_gi);
    cudaGetSymbolAddress((void**)&gh, g_gh);
    cudaGetSymbolAddress((void**)&wihT, g_wihT);
    cudaGetSymbolAddress((void**)&whhT, g_whhT);
    cudaGetSymbolAddress((void**)&wcomb, g_wcomb);

    static cudaStream_t s2 = nullptr, s3 = nullptr;
    static cudaEvent_t evF[2], evJ[2], evP, evW0, evW1;
    if (!s2) {
        cudaStreamCreateWithFlags(&s2, cudaStreamNonBlocking);
        cudaStreamCreateWithFlags(&s3, cudaStreamNonBlocking);
        for (int i = 0; i < 2; i++) {
            cudaEventCreateWithFlags(&evF[i], cudaEventDisableTiming);
            cudaEventCreateWithFlags(&evJ[i], cudaEventDisableTiming);
        }
        cudaEventCreateWithFlags(&evP, cudaEventDisableTiming);
        cudaEventCreateWithFlags(&evW0, cudaEventDisableTiming);
        cudaEventCreateWithFlags(&evW1, cudaEventDisableTiming);
    }

    // ---- prep: transposes, then both wcomb GEMMs concurrently on s2/s3 ----
    transpose_kernel<<<(3 * D * D + 255) / 256, 256>>>(w_ih, wihT);
    transpose_kernel<<<(3 * D * D + 255) / 256, 256>>>(w_hh, whhT);
    cudaEventRecord(evP, 0);
    cudaStreamWaitEvent(s2, evP, 0);
    cudaStreamWaitEvent(s3, evP, 0);
    gemm128<<<dim3(3, 1), 256, 0, s2>>>(conv_w, wihT, wcomb, D, 3 * D);
    cudaEventRecord(evW0, s2);
    gemm128<<<dim3(3, 1), 256, 0, s3>>>(conv_w + (size_t)D * D, wihT,
                                        wcomb + (size_t)D * 3 * D, D, 3 * D);
    cudaEventRecord(evW1, s3);

    gather_kernel<<<(N * 32 + 255) / 256, 256>>>(node_ids, (const float4*)embed,
                                                 (float4*)h, (float4*)agg, N);

    int rowBlocks = (N + 127) / 128;   // 391

    for (int layer = 0; layer < 2; layer++) {
        // fork: gh = h @ w_hh^T on s2 (overlaps scatter on main)
        cudaEventRecord(evF[layer], 0);
        cudaStreamWaitEvent(s2, evF[layer], 0);
        gemm128<<<dim3(3, rowBlocks), 256, 0, s2>>>(h, whhT, gh, N, 3 * D);
        cudaEventRecord(evJ[layer], s2);

        // main: agg[dst] += h[src]  (persistent, low CTA footprint)
        scatter_kernel<<<592, 256>>>((const float4*)h, src, dst, agg, E);

        // gi = agg @ Wcomb[layer]
        cudaStreamWaitEvent(0, layer == 0 ? evW0 : evW1, 0);
        gemm128<<<dim3(3, rowBlocks), 256>>>(agg, wcomb + (size_t)layer * D * 3 * D,
                                             gi, N, 3 * D);

        // join gh, fuse gates; zero agg for next layer's scatter
        cudaStreamWaitEvent(0, evJ[layer], 0);
        gru_kernel<<<(N * 32 + 255) / 256, 256>>>((const float4*)gi,
                                                  (const float4*)gh,
                                                  (const float4*)b_ih,
                                                  (const float4*)b_hh,
                                                  (float4*)h, (float4*)agg,
                                                  N * 32, layer == 0 ? 1 : 0);
    }

    pool_kernel<<<G, 512>>>(h, batch, out, N);
}

// round 12
// speedup vs baseline: 1.0556x; 1.0556x over previous
#include <cuda_runtime.h>
#include <cuda_bf16.h>
#include <math.h>
#include <stdint.h>

#define D 128
#define MAXN 50000

// ---------------- scratch ----------------
__device__ float g_h[MAXN * D];
__device__ float g_agg[MAXN * D];          // scatter-add of h over edges
__device__ float g_gi[MAXN * 3 * D];
__device__ float g_gh[MAXN * 3 * D];
__device__ float g_wihT[D * 3 * D];        // [K=128][M=384]
__device__ float g_whhT[D * 3 * D];
__device__ float g_wcomb[2 * D * 3 * D];   // conv_w[l] @ w_ihT : [128][384] per layer

// ---------------- weight transpose: WT[k][m] = W[m][k], W is [384,128] ----------------
__global__ void transpose_kernel(const float* __restrict__ W, float* __restrict__ WT) {
    int idx = blockIdx.x * blockDim.x + threadIdx.x;
    if (idx >= 3 * D * D) return;
    int m = idx / D;
    int k = idx % D;
    WT[(size_t)k * (3 * D) + m] = W[idx];
}

// ---------------- FFMA register-blocked GEMM (proven R8/R10 version, BK=16) ----------------
// C[N x M] = A[N x 128] @ B[128 x M]; M multiple of 128.
#define BK 16
__global__ __launch_bounds__(256, 2)
void gemm128(const float* __restrict__ A, const float* __restrict__ B,
             float* __restrict__ C, int N, int M) {
    __shared__ float As[BK][132];   // transposed As[k][m]
    __shared__ float Bs[BK][128];   // Bs[k][n]

    int tid = threadIdx.x;
    int block_row = blockIdx.y * 128;
    int block_col = blockIdx.x * 128;

    int aRow = tid >> 2;
    int aCol = (tid & 3) * 4;
    int bRow = tid >> 5;
    int bCol = (tid & 31) * 4;
    int tr = (tid >> 4) * 4;
    int tc = (tid & 15) * 4;

    float acc[8][8];
#pragma unroll
    for (int i = 0; i < 8; i++)
#pragma unroll
        for (int j = 0; j < 8; j++) acc[i][j] = 0.0f;

    for (int k0 = 0; k0 < 128; k0 += BK) {
#pragma unroll
        for (int p = 0; p < 2; p++) {
            int r = aRow + p * 64;
            int gr = block_row + r;
            float4 v = make_float4(0.f, 0.f, 0.f, 0.f);
            if (gr < N) v = *(const float4*)(A + (size_t)gr * 128 + k0 + aCol);
            As[aCol + 0][r] = v.x;
            As[aCol + 1][r] = v.y;
            As[aCol + 2][r] = v.z;
            As[aCol + 3][r] = v.w;
        }
#pragma unroll
        for (int p = 0; p < 2; p++) {
            int r = bRow + p * 8;
            float4 v = *(const float4*)(B + (size_t)(k0 + r) * M + block_col + bCol);
            *(float4*)&Bs[r][bCol] = v;
        }
        __syncthreads();

#pragma unroll
        for (int k = 0; k < BK; k++) {
            float4 m0 = *(const float4*)&As[k][tr];
            float4 m1 = *(const float4*)&As[k][tr + 64];
            float4 n0 = *(const float4*)&Bs[k][tc];
            float4 n1 = *(const float4*)&Bs[k][tc + 64];
            float rm[8] = {m0.x, m0.y, m0.z, m0.w, m1.x, m1.y, m1.z, m1.w};
            float rn[8] = {n0.x, n0.y, n0.z, n0.w, n1.x, n1.y, n1.z, n1.w};
#pragma unroll
            for (int i = 0; i < 8; i++)
#pragma unroll
                for (int j = 0; j < 8; j++)
                    acc[i][j] = fmaf(rm[i], rn[j], acc[i][j]);
        }
        __syncthreads();
    }

#pragma unroll
    for (int ii = 0; ii < 2; ii++) {
#pragma unroll
        for (int i = 0; i < 4; i++) {
            int row = block_row + tr + ii * 64 + i;
            if (row >= N) continue;
#pragma unroll
            for (int jj = 0; jj < 2; jj++) {
                int col = block_col + tc + jj * 64;
                float4 r;
                r.x = acc[ii * 4 + i][jj * 4 + 0];
                r.y = acc[ii * 4 + i][jj * 4 + 1];
                r.z = acc[ii * 4 + i][jj * 4 + 2];
                r.w = acc[ii * 4 + i][jj * 4 + 3];
                *(float4*)&C[(size_t)row * M + col] = r;
            }
        }
    }
}

// ---------------- gather: h = embed[node_ids]; also zero agg ----------------
__global__ void gather_kernel(const int* __restrict__ node_ids,
                              const float4* __restrict__ embed4,
                              float4* __restrict__ h4,
                              float4* __restrict__ agg4, int N) {
    int idx = blockIdx.x * blockDim.x + threadIdx.x;
    if (idx >= N * 32) return;
    int n = idx >> 5;
    int c = idx & 31;
    int id = node_ids[n];
    h4[(size_t)n * 32 + c] = embed4[(size_t)id * 32 + c];
    agg4[idx] = make_float4(0.f, 0.f, 0.f, 0.f);
}

// ---------------- edge scatter: agg[dst] += h[src], 4 edges/warp (R10 version) ----------------
#define RED4(P, V)                                                         \
    asm volatile("red.global.add.v4.f32 [%0], {%1, %2, %3, %4};"           \
                 :: "l"(P), "f"((V).x), "f"((V).y), "f"((V).z), "f"((V).w) \
                 : "memory")

__global__ void scatter_kernel(const float4* __restrict__ h4,
                               const int* __restrict__ src,
                               const int* __restrict__ dst,
                               float* __restrict__ agg, int E) {
    int w = blockIdx.x * (blockDim.x >> 5) + (threadIdx.x >> 5);
    int lane = threadIdx.x & 31;
    int e0 = w * 4;
    if (e0 >= E) return;
    if (e0 + 4 <= E) {
        int s0 = __ldg(src + e0 + 0), s1 = __ldg(src + e0 + 1);
        int s2 = __ldg(src + e0 + 2), s3 = __ldg(src + e0 + 3);
        int d0 = __ldg(dst + e0 + 0), d1 = __ldg(dst + e0 + 1);
        int d2 = __ldg(dst + e0 + 2), d3 = __ldg(dst + e0 + 3);
        float4 v0 = h4[(size_t)s0 * 32 + lane];
        float4 v1 = h4[(size_t)s1 * 32 + lane];
        float4 v2 = h4[(size_t)s2 * 32 + lane];
        float4 v3 = h4[(size_t)s3 * 32 + lane];
        RED4(agg + (size_t)d0 * D + lane * 4, v0);
        RED4(agg + (size_t)d1 * D + lane * 4, v1);
        RED4(agg + (size_t)d2 * D + lane * 4, v2);
        RED4(agg + (size_t)d3 * D + lane * 4, v3);
    } else {
        for (int e = e0; e < E; e++) {
            int s = __ldg(src + e);
            int d = __ldg(dst + e);
            float4 v = h4[(size_t)s * 32 + lane];
            RED4(agg + (size_t)d * D + lane * 4, v);
        }
    }
}

// ---------------- GRU gate fusion (biases folded); optionally zero agg ----------------
__global__ void gru_kernel(const float4* __restrict__ gi4,
                           const float4* __restrict__ gh4,
                           const float4* __restrict__ bih4,
                           const float4* __restrict__ bhh4,
                           float4* __restrict__ h4,
                           float4* __restrict__ agg4,
                           int total4, int zero_agg) {
    int idx = blockIdx.x * blockDim.x + threadIdx.x;
    if (idx >= total4) return;
    int n = idx >> 5;
    int c = idx & 31;
    const float4* gin = gi4 + (size_t)n * 96;
    const float4* ghn = gh4 + (size_t)n * 96;
    float4 ir = gin[c], iz = gin[c + 32], in_ = gin[c + 64];
    float4 hr = ghn[c], hz = ghn[c + 32], hn = ghn[c + 64];
    float4 bir = bih4[c], biz = bih4[c + 32], bin = bih4[c + 64];
    float4 bhr = bhh4[c], bhz = bhh4[c + 32], bhn = bhh4[c + 64];
    float4 h = h4[idx];
    float4 o;
#define GRU1(X)                                                                 \
    {                                                                           \
        float r = 1.0f / (1.0f + __expf(-(ir.X + bir.X + hr.X + bhr.X)));       \
        float z = 1.0f / (1.0f + __expf(-(iz.X + biz.X + hz.X + bhz.X)));       \
        float nn = tanhf(in_.X + bin.X + r * (hn.X + bhn.X));                   \
        o.X = (1.0f - z) * nn + z * h.X;                                        \
    }
    GRU1(x) GRU1(y) GRU1(z) GRU1(w)
#undef GRU1
    h4[idx] = o;
    if (zero_agg) agg4[idx] = make_float4(0.f, 0.f, 0.f, 0.f);
}

// ---------------- per-graph mean pool (batch sorted) ----------------
__device__ __forceinline__ int lower_bound_dev(const int* a, int n, int key) {
    int lo = 0, hi = n;
    while (lo < hi) {
        int mid = (lo + hi) >> 1;
        if (a[mid] < key) lo = mid + 1; else hi = mid;
    }
    return lo;
}

__global__ void pool_kernel(const float* __restrict__ h,
                            const int* __restrict__ batch,
                            float* __restrict__ out, int N) {
    int g = blockIdx.x;
    int tid = threadIdx.x;
    int sub = tid >> 7;
    int d = tid & 127;
    __shared__ int s_lo, s_hi;
    __shared__ float sbuf[4][128];
    if (tid == 0) {
        s_lo = lower_bound_dev(batch, N, g);
        s_hi = lower_bound_dev(batch, N, g + 1);
    }
    __syncthreads();
    int lo = s_lo, hi = s_hi;
    float acc = 0.0f;
    for (int n = lo + sub; n < hi; n += 4)
        acc += h[(size_t)n * D + d];
    sbuf[sub][d] = acc;
    __syncthreads();
    if (sub == 0) {
        float total = sbuf[0][d] + sbuf[1][d] + sbuf[2][d] + sbuf[3][d];
        float cnt = (float)(hi - lo);
        out[(size_t)g * D + d] = total / fmaxf(cnt, 1.0f);
    }
}

// ---------------- launch ----------------
extern "C" void kernel_launch(void* const* d_in, const int* in_sizes, int n_in,
                              void* d_out, int out_size) {
    const int* node_ids = (const int*)d_in[0];
    const int* edge_index = (const int*)d_in[1];
    const int* batch = (const int*)d_in[2];
    const float* embed = (const float*)d_in[4];
    const float* conv_w = (const float*)d_in[5];   // [2][K=128][M=128]
    const float* w_ih = (const float*)d_in[6];
    const float* w_hh = (const float*)d_in[7];
    const float* b_ih = (const float*)d_in[8];
    const float* b_hh = (const float*)d_in[9];
    float* out = (float*)d_out;

    int N = in_sizes[0];
    int E = in_sizes[1] / 2;
    int G = out_size / D;
    const int* src = edge_index;
    const int* dst = edge_index + E;

    float *h, *agg, *gi, *gh, *wihT, *whhT, *wcomb;
    cudaGetSymbolAddress((void**)&h, g_h);
    cudaGetSymbolAddress((void**)&agg, g_agg);
    cudaGetSymbolAddress((void**)&gi, g_gi);
    cudaGetSymbolAddress((void**)&gh, g_gh);
    cudaGetSymbolAddress((void**)&wihT, g_wihT);
    cudaGetSymbolAddress((void**)&whhT, g_whhT);
    cudaGetSymbolAddress((void**)&wcomb, g_wcomb);

    static cudaStream_t s2 = nullptr, s3 = nullptr;
    static cudaEvent_t evF[2], evJ[2], evP, evW0, evW1;
    if (!s2) {
        cudaStreamCreateWithFlags(&s2, cudaStreamNonBlocking);
        cudaStreamCreateWithFlags(&s3, cudaStreamNonBlocking);
        for (int i = 0; i < 2; i++) {
            cudaEventCreateWithFlags(&evF[i], cudaEventDisableTiming);
            cudaEventCreateWithFlags(&evJ[i], cudaEventDisableTiming);
        }
        cudaEventCreateWithFlags(&evP, cudaEventDisableTiming);
        cudaEventCreateWithFlags(&evW0, cudaEventDisableTiming);
        cudaEventCreateWithFlags(&evW1, cudaEventDisableTiming);
    }

    // ---- prep: transposes, then both wcomb GEMMs concurrently on s2/s3 ----
    transpose_kernel<<<(3 * D * D + 255) / 256, 256>>>(w_ih, wihT);
    transpose_kernel<<<(3 * D * D + 255) / 256, 256>>>(w_hh, whhT);
    cudaEventRecord(evP, 0);
    cudaStreamWaitEvent(s2, evP, 0);
    cudaStreamWaitEvent(s3, evP, 0);
    gemm128<<<dim3(3, 1), 256, 0, s2>>>(conv_w, wihT, wcomb, D, 3 * D);
    cudaEventRecord(evW0, s2);
    gemm128<<<dim3(3, 1), 256, 0, s3>>>(conv_w + (size_t)D * D, wihT,
                                        wcomb + (size_t)D * 3 * D, D, 3 * D);
    cudaEventRecord(evW1, s3);

    gather_kernel<<<(N * 32 + 255) / 256, 256>>>(node_ids, (const float4*)embed,
                                                 (float4*)h, (float4*)agg, N);

    int rowBlocks = (N + 127) / 128;   // 391

    for (int layer = 0; layer < 2; layer++) {
        // fork: gh = h @ w_hh^T on s2 (overlaps scatter on main)
        cudaEventRecord(evF[layer], 0);
        cudaStreamWaitEvent(s2, evF[layer], 0);
        gemm128<<<dim3(3, rowBlocks), 256, 0, s2>>>(h, whhT, gh, N, 3 * D);
        cudaEventRecord(evJ[layer], s2);

        // main: agg[dst] += h[src]  (full-grid ILP-4, proven R10 config)
        {
            int warps = (E + 3) / 4;
            int blocks = (warps + 7) / 8;
            scatter_kernel<<<blocks, 256>>>((const float4*)h, src, dst, agg, E);
        }

        // gi = agg @ Wcomb[layer]
        cudaStreamWaitEvent(0, layer == 0 ? evW0 : evW1, 0);
        gemm128<<<dim3(3, rowBlocks), 256>>>(agg, wcomb + (size_t)layer * D * 3 * D,
                                             gi, N, 3 * D);

        // join gh, fuse gates; zero agg for next layer's scatter
        cudaStreamWaitEvent(0, evJ[layer], 0);
        gru_kernel<<<(N * 32 + 255) / 256, 256>>>((const float4*)gi,
                                                  (const float4*)gh,
                                                  (const float4*)b_ih,
                                                  (const float4*)b_hh,
                                                  (float4*)h, (float4*)agg,
                                                  N * 32, layer == 0 ? 1 : 0);
    }

    pool_kernel<<<G, 512>>>(h, batch, out, N);
}

// round 13
// speedup vs baseline: 1.1967x; 1.1337x over previous
#include <cuda_runtime.h>
#include <cuda_bf16.h>
#include <math.h>
#include <stdint.h>

#define D 128
#define MAXN 50000

// ---------------- scratch ----------------
__device__ float g_h[MAXN * D];
__device__ float g_agg[MAXN * D];          // scatter-add of h over edges
__device__ float g_gi[MAXN * 3 * D];
__device__ float g_gh[MAXN * 3 * D];
__device__ float g_wihT[D * 3 * D];        // [K=128][M=384]
__device__ float g_whhT[D * 3 * D];
__device__ float g_wcomb[2 * D * 3 * D];   // conv_w[l] @ w_ihT : [128][384] per layer

// ---------------- weight transpose: WT[k][m] = W[m][k], W is [384,128] ----------------
__global__ void transpose_kernel(const float* __restrict__ W, float* __restrict__ WT) {
    int idx = blockIdx.x * blockDim.x + threadIdx.x;
    if (idx >= 3 * D * D) return;
    int m = idx / D;
    int k = idx % D;
    WT[(size_t)k * (3 * D) + m] = W[idx];
}

// ---------------- FFMA2 (f32x2) register-blocked GEMM ----------------
// C[N x M] = A[N x 128] @ B[128 x M]; M multiple of 128.
// Same tiling as proven BK=16 kernel; inner product uses packed fma.rn.f32x2:
// accumulator pairs along j (columns), rm lane-duplicated.
#define BK 16
__global__ __launch_bounds__(256, 2)
void gemm128(const float* __restrict__ A, const float* __restrict__ B,
             float* __restrict__ C, int N, int M) {
    __shared__ float As[BK][132];   // transposed As[k][m]
    __shared__ float Bs[BK][128];   // Bs[k][n]

    int tid = threadIdx.x;
    int block_row = blockIdx.y * 128;
    int block_col = blockIdx.x * 128;

    int aRow = tid >> 2;
    int aCol = (tid & 3) * 4;
    int bRow = tid >> 5;
    int bCol = (tid & 31) * 4;
    int tr = (tid >> 4) * 4;
    int tc = (tid & 15) * 4;

    // acc2[i][jp]: packed pair of columns (2*jp, 2*jp+1) within the 8-col set
    uint64_t acc2[8][4];
#pragma unroll
    for (int i = 0; i < 8; i++)
#pragma unroll
        for (int j = 0; j < 4; j++) acc2[i][j] = 0ULL;

    for (int k0 = 0; k0 < 128; k0 += BK) {
#pragma unroll
        for (int p = 0; p < 2; p++) {
            int r = aRow + p * 64;
            int gr = block_row + r;
            float4 v = make_float4(0.f, 0.f, 0.f, 0.f);
            if (gr < N) v = *(const float4*)(A + (size_t)gr * 128 + k0 + aCol);
            As[aCol + 0][r] = v.x;
            As[aCol + 1][r] = v.y;
            As[aCol + 2][r] = v.z;
            As[aCol + 3][r] = v.w;
        }
#pragma unroll
        for (int p = 0; p < 2; p++) {
            int r = bRow + p * 8;
            float4 v = *(const float4*)(B + (size_t)(k0 + r) * M + block_col + bCol);
            *(float4*)&Bs[r][bCol] = v;
        }
        __syncthreads();

#pragma unroll
        for (int k = 0; k < BK; k++) {
            float4 m0 = *(const float4*)&As[k][tr];
            float4 m1 = *(const float4*)&As[k][tr + 64];
            // rn pairs straight from smem as 64-bit lanes
            const uint64_t* b0 = (const uint64_t*)&Bs[k][tc];        // cols tc,tc+1 / tc+2,tc+3
            const uint64_t* b1 = (const uint64_t*)&Bs[k][tc + 64];
            uint64_t bn[4] = {b0[0], b0[1], b1[0], b1[1]};
            float rm[8] = {m0.x, m0.y, m0.z, m0.w, m1.x, m1.y, m1.z, m1.w};
#pragma unroll
            for (int i = 0; i < 8; i++) {
                uint64_t rm2;
                uint32_t mu = __float_as_uint(rm[i]);
                asm("mov.b64 %0, {%1, %1};" : "=l"(rm2) : "r"(mu));
#pragma unroll
                for (int j = 0; j < 4; j++)
                    asm("fma.rn.f32x2 %0, %1, %2, %0;"
                        : "+l"(acc2[i][j]) : "l"(rm2), "l"(bn[j]));
            }
        }
        __syncthreads();
    }

#pragma unroll
    for (int ii = 0; ii < 2; ii++) {
#pragma unroll
        for (int i = 0; i < 4; i++) {
            int row = block_row + tr + ii * 64 + i;
            if (row >= N) continue;
#pragma unroll
            for (int jj = 0; jj < 2; jj++) {
                int col = block_col + tc + jj * 64;
                uint64_t p0 = acc2[ii * 4 + i][jj * 2 + 0];
                uint64_t p1 = acc2[ii * 4 + i][jj * 2 + 1];
                float4 r;
                r.x = __uint_as_float((uint32_t)p0);
                r.y = __uint_as_float((uint32_t)(p0 >> 32));
                r.z = __uint_as_float((uint32_t)p1);
                r.w = __uint_as_float((uint32_t)(p1 >> 32));
                *(float4*)&C[(size_t)row * M + col] = r;
            }
        }
    }
}

// ---------------- gather: h = embed[node_ids]; also zero agg ----------------
__global__ void gather_kernel(const int* __restrict__ node_ids,
                              const float4* __restrict__ embed4,
                              float4* __restrict__ h4,
                              float4* __restrict__ agg4, int N) {
    int idx = blockIdx.x * blockDim.x + threadIdx.x;
    if (idx >= N * 32) return;
    int n = idx >> 5;
    int c = idx & 31;
    int id = node_ids[n];
    h4[(size_t)n * 32 + c] = embed4[(size_t)id * 32 + c];
    agg4[idx] = make_float4(0.f, 0.f, 0.f, 0.f);
}

// ---------------- edge scatter: agg[dst] += h[src], 4 edges/warp ----------------
#define RED4(P, V)                                                         \
    asm volatile("red.global.add.v4.f32 [%0], {%1, %2, %3, %4};"           \
                 :: "l"(P), "f"((V).x), "f"((V).y), "f"((V).z), "f"((V).w) \
                 : "memory")

__global__ void scatter_kernel(const float4* __restrict__ h4,
                               const int* __restrict__ src,
                               const int* __restrict__ dst,
                               float* __restrict__ agg, int E) {
    int w = blockIdx.x * (blockDim.x >> 5) + (threadIdx.x >> 5);
    int lane = threadIdx.x & 31;
    int e0 = w * 4;
    if (e0 >= E) return;
    if (e0 + 4 <= E) {
        int s0 = __ldg(src + e0 + 0), s1 = __ldg(src + e0 + 1);
        int s2 = __ldg(src + e0 + 2), s3 = __ldg(src + e0 + 3);
        int d0 = __ldg(dst + e0 + 0), d1 = __ldg(dst + e0 + 1);
        int d2 = __ldg(dst + e0 + 2), d3 = __ldg(dst + e0 + 3);
        float4 v0 = h4[(size_t)s0 * 32 + lane];
        float4 v1 = h4[(size_t)s1 * 32 + lane];
        float4 v2 = h4[(size_t)s2 * 32 + lane];
        float4 v3 = h4[(size_t)s3 * 32 + lane];
        RED4(agg + (size_t)d0 * D + lane * 4, v0);
        RED4(agg + (size_t)d1 * D + lane * 4, v1);
        RED4(agg + (size_t)d2 * D + lane * 4, v2);
        RED4(agg + (size_t)d3 * D + lane * 4, v3);
    } else {
        for (int e = e0; e < E; e++) {
            int s = __ldg(src + e);
            int d = __ldg(dst + e);
            float4 v = h4[(size_t)s * 32 + lane];
            RED4(agg + (size_t)d * D + lane * 4, v);
        }
    }
}

// ---------------- GRU gate fusion (biases folded); optionally zero agg ----------------
__global__ void gru_kernel(const float4* __restrict__ gi4,
                           const float4* __restrict__ gh4,
                           const float4* __restrict__ bih4,
                           const float4* __restrict__ bhh4,
                           float4* __restrict__ h4,
                           float4* __restrict__ agg4,
                           int total4, int zero_agg) {
    int idx = blockIdx.x * blockDim.x + threadIdx.x;
    if (idx >= total4) return;
    int n = idx >> 5;
    int c = idx & 31;
    const float4* gin = gi4 + (size_t)n * 96;
    const float4* ghn = gh4 + (size_t)n * 96;
    float4 ir = gin[c], iz = gin[c + 32], in_ = gin[c + 64];
    float4 hr = ghn[c], hz = ghn[c + 32], hn = ghn[c + 64];
    float4 bir = bih4[c], biz = bih4[c + 32], bin = bih4[c + 64];
    float4 bhr = bhh4[c], bhz = bhh4[c + 32], bhn = bhh4[c + 64];
    float4 h = h4[idx];
    float4 o;
#define GRU1(X)                                                                 \
    {                                                                           \
        float r = 1.0f / (1.0f + __expf(-(ir.X + bir.X + hr.X + bhr.X)));       \
        float z = 1.0f / (1.0f + __expf(-(iz.X + biz.X + hz.X + bhz.X)));       \
        float nn = tanhf(in_.X + bin.X + r * (hn.X + bhn.X));                   \
        o.X = (1.0f - z) * nn + z * h.X;                                        \
    }
    GRU1(x) GRU1(y) GRU1(z) GRU1(w)
#undef GRU1
    h4[idx] = o;
    if (zero_agg) agg4[idx] = make_float4(0.f, 0.f, 0.f, 0.f);
}

// ---------------- per-graph mean pool (batch sorted) ----------------
__device__ __forceinline__ int lower_bound_dev(const int* a, int n, int key) {
    int lo = 0, hi = n;
    while (lo < hi) {
        int mid = (lo + hi) >> 1;
        if (a[mid] < key) lo = mid + 1; else hi = mid;
    }
    return lo;
}

__global__ void pool_kernel(const float* __restrict__ h,
                            const int* __restrict__ batch,
                            float* __restrict__ out, int N) {
    int g = blockIdx.x;
    int tid = threadIdx.x;
    int sub = tid >> 7;
    int d = tid & 127;
    __shared__ int s_lo, s_hi;
    __shared__ float sbuf[4][128];
    if (tid == 0) {
        s_lo = lower_bound_dev(batch, N, g);
        s_hi = lower_bound_dev(batch, N, g + 1);
    }
    __syncthreads();
    int lo = s_lo, hi = s_hi;
    float acc = 0.0f;
    for (int n = lo + sub; n < hi; n += 4)
        acc += h[(size_t)n * D + d];
    sbuf[sub][d] = acc;
    __syncthreads();
    if (sub == 0) {
        float total = sbuf[0][d] + sbuf[1][d] + sbuf[2][d] + sbuf[3][d];
        float cnt = (float)(hi - lo);
        out[(size_t)g * D + d] = total / fmaxf(cnt, 1.0f);
    }
}

// ---------------- launch ----------------
extern "C" void kernel_launch(void* const* d_in, const int* in_sizes, int n_in,
                              void* d_out, int out_size) {
    const int* node_ids = (const int*)d_in[0];
    const int* edge_index = (const int*)d_in[1];
    const int* batch = (const int*)d_in[2];
    const float* embed = (const float*)d_in[4];
    const float* conv_w = (const float*)d_in[5];   // [2][K=128][M=128]
    const float* w_ih = (const float*)d_in[6];
    const float* w_hh = (const float*)d_in[7];
    const float* b_ih = (const float*)d_in[8];
    const float* b_hh = (const float*)d_in[9];
    float* out = (float*)d_out;

    int N = in_sizes[0];
    int E = in_sizes[1] / 2;
    int G = out_size / D;
    const int* src = edge_index;
    const int* dst = edge_index + E;

    float *h, *agg, *gi, *gh, *wihT, *whhT, *wcomb;
    cudaGetSymbolAddress((void**)&h, g_h);
    cudaGetSymbolAddress((void**)&agg, g_agg);
    cudaGetSymbolAddress((void**)&gi, g_gi);
    cudaGetSymbolAddress((void**)&gh, g_gh);
    cudaGetSymbolAddress((void**)&wihT, g_wihT);
    cudaGetSymbolAddress((void**)&whhT, g_whhT);
    cudaGetSymbolAddress((void**)&wcomb, g_wcomb);

    static cudaStream_t s2 = nullptr, s3 = nullptr;
    static cudaEvent_t evF[2], evJ[2], evP, evW0, evW1;
    if (!s2) {
        cudaStreamCreateWithFlags(&s2, cudaStreamNonBlocking);
        cudaStreamCreateWithFlags(&s3, cudaStreamNonBlocking);
        for (int i = 0; i < 2; i++) {
            cudaEventCreateWithFlags(&evF[i], cudaEventDisableTiming);
            cudaEventCreateWithFlags(&evJ[i], cudaEventDisableTiming);
        }
        cudaEventCreateWithFlags(&evP, cudaEventDisableTiming);
        cudaEventCreateWithFlags(&evW0, cudaEventDisableTiming);
        cudaEventCreateWithFlags(&evW1, cudaEventDisableTiming);
    }

    // ---- prep: transposes, then both wcomb GEMMs concurrently on s2/s3 ----
    transpose_kernel<<<(3 * D * D + 255) / 256, 256>>>(w_ih, wihT);
    transpose_kernel<<<(3 * D * D + 255) / 256, 256>>>(w_hh, whhT);
    cudaEventRecord(evP, 0);
    cudaStreamWaitEvent(s2, evP, 0);
    cudaStreamWaitEvent(s3, evP, 0);
    gemm128<<<dim3(3, 1), 256, 0, s2>>>(conv_w, wihT, wcomb, D, 3 * D);
    cudaEventRecord(evW0, s2);
    gemm128<<<dim3(3, 1), 256, 0, s3>>>(conv_w + (size_t)D * D, wihT,
                                        wcomb + (size_t)D * 3 * D, D, 3 * D);
    cudaEventRecord(evW1, s3);

    gather_kernel<<<(N * 32 + 255) / 256, 256>>>(node_ids, (const float4*)embed,
                                                 (float4*)h, (float4*)agg, N);

    int rowBlocks = (N + 127) / 128;   // 391

    for (int layer = 0; layer < 2; layer++) {
        // fork: gh = h @ w_hh^T on s2 (overlaps scatter on main)
        cudaEventRecord(evF[layer], 0);
        cudaStreamWaitEvent(s2, evF[layer], 0);
        gemm128<<<dim3(3, rowBlocks), 256, 0, s2>>>(h, whhT, gh, N, 3 * D);
        cudaEventRecord(evJ[layer], s2);

        // main: agg[dst] += h[src]
        {
            int warps = (E + 3) / 4;
            int blocks = (warps + 7) / 8;
            scatter_kernel<<<blocks, 256>>>((const float4*)h, src, dst, agg, E);
        }

        // gi = agg @ Wcomb[layer]
        cudaStreamWaitEvent(0, layer == 0 ? evW0 : evW1, 0);
        gemm128<<<dim3(3, rowBlocks), 256>>>(agg, wcomb + (size_t)layer * D * 3 * D,
                                             gi, N, 3 * D);

        // join gh, fuse gates; zero agg for next layer's scatter
        cudaStreamWaitEvent(0, evJ[layer], 0);
        gru_kernel<<<(N * 32 + 255) / 256, 256>>>((const float4*)gi,
                                                  (const float4*)gh,
                                                  (const float4*)b_ih,
                                                  (const float4*)b_hh,
                                                  (float4*)h, (float4*)agg,
                                                  N * 32, layer == 0 ? 1 : 0);
    }

    pool_kernel<<<G, 512>>>(h, batch, out, N);
}

// round 14
// speedup vs baseline: 1.2010x; 1.0036x over previous
#include <cuda_runtime.h>
#include <cuda_bf16.h>
#include <math.h>
#include <stdint.h>

#define D 128
#define MAXN 50000

// ---------------- scratch ----------------
__device__ float g_h[MAXN * D];
__device__ float g_agg[MAXN * D];          // scatter-add of h over edges
__device__ float g_gi[MAXN * 3 * D];
__device__ float g_gh[MAXN * 3 * D];
__device__ float g_wihT[D * 3 * D];        // [K=128][M=384]
__device__ float g_whhT[D * 3 * D];
__device__ float g_wcomb[2 * D * 3 * D];   // conv_w[l] @ w_ihT : [128][384] per layer

// ---------------- weight transpose: WT[k][m] = W[m][k], W is [384,128] ----------------
__global__ void transpose_kernel(const float* __restrict__ W, float* __restrict__ WT) {
    int idx = blockIdx.x * blockDim.x + threadIdx.x;
    if (idx >= 3 * D * D) return;
    int m = idx / D;
    int k = idx % D;
    WT[(size_t)k * (3 * D) + m] = W[idx];
}

// ---------------- FFMA2 (f32x2) register-blocked GEMM (proven R13) ----------------
// C[N x M] = A[N x 128] @ B[128 x M]; M multiple of 128.
#define BK 16
__global__ __launch_bounds__(256, 2)
void gemm128(const float* __restrict__ A, const float* __restrict__ B,
             float* __restrict__ C, int N, int M) {
    __shared__ float As[BK][132];   // transposed As[k][m]
    __shared__ float Bs[BK][128];   // Bs[k][n]

    int tid = threadIdx.x;
    int block_row = blockIdx.y * 128;
    int block_col = blockIdx.x * 128;

    int aRow = tid >> 2;
    int aCol = (tid & 3) * 4;
    int bRow = tid >> 5;
    int bCol = (tid & 31) * 4;
    int tr = (tid >> 4) * 4;
    int tc = (tid & 15) * 4;

    uint64_t acc2[8][4];
#pragma unroll
    for (int i = 0; i < 8; i++)
#pragma unroll
        for (int j = 0; j < 4; j++) acc2[i][j] = 0ULL;

    for (int k0 = 0; k0 < 128; k0 += BK) {
#pragma unroll
        for (int p = 0; p < 2; p++) {
            int r = aRow + p * 64;
            int gr = block_row + r;
            float4 v = make_float4(0.f, 0.f, 0.f, 0.f);
            if (gr < N) v = *(const float4*)(A + (size_t)gr * 128 + k0 + aCol);
            As[aCol + 0][r] = v.x;
            As[aCol + 1][r] = v.y;
            As[aCol + 2][r] = v.z;
            As[aCol + 3][r] = v.w;
        }
#pragma unroll
        for (int p = 0; p < 2; p++) {
            int r = bRow + p * 8;
            float4 v = *(const float4*)(B + (size_t)(k0 + r) * M + block_col + bCol);
            *(float4*)&Bs[r][bCol] = v;
        }
        __syncthreads();

#pragma unroll
        for (int k = 0; k < BK; k++) {
            float4 m0 = *(const float4*)&As[k][tr];
            float4 m1 = *(const float4*)&As[k][tr + 64];
            const uint64_t* b0 = (const uint64_t*)&Bs[k][tc];
            const uint64_t* b1 = (const uint64_t*)&Bs[k][tc + 64];
            uint64_t bn[4] = {b0[0], b0[1], b1[0], b1[1]};
            float rm[8] = {m0.x, m0.y, m0.z, m0.w, m1.x, m1.y, m1.z, m1.w};
#pragma unroll
            for (int i = 0; i < 8; i++) {
                uint64_t rm2;
                uint32_t mu = __float_as_uint(rm[i]);
                asm("mov.b64 %0, {%1, %1};" : "=l"(rm2) : "r"(mu));
#pragma unroll
                for (int j = 0; j < 4; j++)
                    asm("fma.rn.f32x2 %0, %1, %2, %0;"
                        : "+l"(acc2[i][j]) : "l"(rm2), "l"(bn[j]));
            }
        }
        __syncthreads();
    }

#pragma unroll
    for (int ii = 0; ii < 2; ii++) {
#pragma unroll
        for (int i = 0; i < 4; i++) {
            int row = block_row + tr + ii * 64 + i;
            if (row >= N) continue;
#pragma unroll
            for (int jj = 0; jj < 2; jj++) {
                int col = block_col + tc + jj * 64;
                uint64_t p0 = acc2[ii * 4 + i][jj * 2 + 0];
                uint64_t p1 = acc2[ii * 4 + i][jj * 2 + 1];
                float4 r;
                r.x = __uint_as_float((uint32_t)p0);
                r.y = __uint_as_float((uint32_t)(p0 >> 32));
                r.z = __uint_as_float((uint32_t)p1);
                r.w = __uint_as_float((uint32_t)(p1 >> 32));
                *(float4*)&C[(size_t)row * M + col] = r;
            }
        }
    }
}

// ---------------- gather: h = embed[node_ids]; also zero agg ----------------
__global__ void gather_kernel(const int* __restrict__ node_ids,
                              const float4* __restrict__ embed4,
                              float4* __restrict__ h4,
                              float4* __restrict__ agg4, int N) {
    int idx = blockIdx.x * blockDim.x + threadIdx.x;
    if (idx >= N * 32) return;
    int n = idx >> 5;
    int c = idx & 31;
    int id = node_ids[n];
    h4[(size_t)n * 32 + c] = embed4[(size_t)id * 32 + c];
    agg4[idx] = make_float4(0.f, 0.f, 0.f, 0.f);
}

// ---------------- edge scatter: agg[dst] += h[src], 8 edges/warp (MLP=8) ----------------
#define RED4(P, V)                                                         \
    asm volatile("red.global.add.v4.f32 [%0], {%1, %2, %3, %4};"           \
                 :: "l"(P), "f"((V).x), "f"((V).y), "f"((V).z), "f"((V).w) \
                 : "memory")

__global__ void scatter_kernel(const float4* __restrict__ h4,
                               const int* __restrict__ src,
                               const int* __restrict__ dst,
                               float* __restrict__ agg, int E) {
    int w = blockIdx.x * (blockDim.x >> 5) + (threadIdx.x >> 5);
    int lane = threadIdx.x & 31;
    int e0 = w * 8;
    if (e0 >= E) return;
    if (e0 + 8 <= E) {
        int s[8], d[8];
#pragma unroll
        for (int i = 0; i < 8; i++) s[i] = __ldg(src + e0 + i);
#pragma unroll
        for (int i = 0; i < 8; i++) d[i] = __ldg(dst + e0 + i);
        float4 v[8];
#pragma unroll
        for (int i = 0; i < 8; i++) v[i] = h4[(size_t)s[i] * 32 + lane];
#pragma unroll
        for (int i = 0; i < 8; i++)
            RED4(agg + (size_t)d[i] * D + lane * 4, v[i]);
    } else {
        for (int e = e0; e < E; e++) {
            int s = __ldg(src + e);
            int d = __ldg(dst + e);
            float4 v = h4[(size_t)s * 32 + lane];
            RED4(agg + (size_t)d * D + lane * 4, v);
        }
    }
}

// ---------------- GRU gate fusion (biases folded); optionally zero agg ----------------
__global__ void gru_kernel(const float4* __restrict__ gi4,
                           const float4* __restrict__ gh4,
                           const float4* __restrict__ bih4,
                           const float4* __restrict__ bhh4,
                           float4* __restrict__ h4,
                           float4* __restrict__ agg4,
                           int total4, int zero_agg) {
    int idx = blockIdx.x * blockDim.x + threadIdx.x;
    if (idx >= total4) return;
    int n = idx >> 5;
    int c = idx & 31;
    const float4* gin = gi4 + (size_t)n * 96;
    const float4* ghn = gh4 + (size_t)n * 96;
    float4 ir = gin[c], iz = gin[c + 32], in_ = gin[c + 64];
    float4 hr = ghn[c], hz = ghn[c + 32], hn = ghn[c + 64];
    float4 bir = bih4[c], biz = bih4[c + 32], bin = bih4[c + 64];
    float4 bhr = bhh4[c], bhz = bhh4[c + 32], bhn = bhh4[c + 64];
    float4 h = h4[idx];
    float4 o;
#define GRU1(X)                                                                 \
    {                                                                           \
        float r = 1.0f / (1.0f + __expf(-(ir.X + bir.X + hr.X + bhr.X)));       \
        float z = 1.0f / (1.0f + __expf(-(iz.X + biz.X + hz.X + bhz.X)));       \
        float nn = tanhf(in_.X + bin.X + r * (hn.X + bhn.X));                   \
        o.X = (1.0f - z) * nn + z * h.X;                                        \
    }
    GRU1(x) GRU1(y) GRU1(z) GRU1(w)
#undef GRU1
    h4[idx] = o;
    if (zero_agg) agg4[idx] = make_float4(0.f, 0.f, 0.f, 0.f);
}

// ---------------- per-graph mean pool (batch sorted) ----------------
__device__ __forceinline__ int lower_bound_dev(const int* a, int n, int key) {
    int lo = 0, hi = n;
    while (lo < hi) {
        int mid = (lo + hi) >> 1;
        if (a[mid] < key) lo = mid + 1; else hi = mid;
    }
    return lo;
}

__global__ void pool_kernel(const float* __restrict__ h,
                            const int* __restrict__ batch,
                            float* __restrict__ out, int N) {
    int g = blockIdx.x;
    int tid = threadIdx.x;
    int sub = tid >> 7;
    int d = tid & 127;
    __shared__ int s_lo, s_hi;
    __shared__ float sbuf[4][128];
    if (tid == 0) {
        s_lo = lower_bound_dev(batch, N, g);
        s_hi = lower_bound_dev(batch, N, g + 1);
    }
    __syncthreads();
    int lo = s_lo, hi = s_hi;
    float acc = 0.0f;
    for (int n = lo + sub; n < hi; n += 4)
        acc += h[(size_t)n * D + d];
    sbuf[sub][d] = acc;
    __syncthreads();
    if (sub == 0) {
        float total = sbuf[0][d] + sbuf[1][d] + sbuf[2][d] + sbuf[3][d];
        float cnt = (float)(hi - lo);
        out[(size_t)g * D + d] = total / fmaxf(cnt, 1.0f);
    }
}

// ---------------- launch ----------------
extern "C" void kernel_launch(void* const* d_in, const int* in_sizes, int n_in,
                              void* d_out, int out_size) {
    const int* node_ids = (const int*)d_in[0];
    const int* edge_index = (const int*)d_in[1];
    const int* batch = (const int*)d_in[2];
    const float* embed = (const float*)d_in[4];
    const float* conv_w = (const float*)d_in[5];   // [2][K=128][M=128]
    const float* w_ih = (const float*)d_in[6];
    const float* w_hh = (const float*)d_in[7];
    const float* b_ih = (const float*)d_in[8];
    const float* b_hh = (const float*)d_in[9];
    float* out = (float*)d_out;

    int N = in_sizes[0];
    int E = in_sizes[1] / 2;
    int G = out_size / D;
    const int* src = edge_index;
    const int* dst = edge_index + E;

    float *h, *agg, *gi, *gh, *wihT, *whhT, *wcomb;
    cudaGetSymbolAddress((void**)&h, g_h);
    cudaGetSymbolAddress((void**)&agg, g_agg);
    cudaGetSymbolAddress((void**)&gi, g_gi);
    cudaGetSymbolAddress((void**)&gh, g_gh);
    cudaGetSymbolAddress((void**)&wihT, g_wihT);
    cudaGetSymbolAddress((void**)&whhT, g_whhT);
    cudaGetSymbolAddress((void**)&wcomb, g_wcomb);

    static cudaStream_t s2 = nullptr, s3 = nullptr;
    static cudaEvent_t evF[2], evJ[2], evP, evW0, evW1;
    if (!s2) {
        cudaStreamCreateWithFlags(&s2, cudaStreamNonBlocking);
        cudaStreamCreateWithFlags(&s3, cudaStreamNonBlocking);
        for (int i = 0; i < 2; i++) {
            cudaEventCreateWithFlags(&evF[i], cudaEventDisableTiming);
            cudaEventCreateWithFlags(&evJ[i], cudaEventDisableTiming);
        }
        cudaEventCreateWithFlags(&evP, cudaEventDisableTiming);
        cudaEventCreateWithFlags(&evW0, cudaEventDisableTiming);
        cudaEventCreateWithFlags(&evW1, cudaEventDisableTiming);
    }

    // ---- prep: transposes, then both wcomb GEMMs concurrently on s2/s3 ----
    transpose_kernel<<<(3 * D * D + 255) / 256, 256>>>(w_ih, wihT);
    transpose_kernel<<<(3 * D * D + 255) / 256, 256>>>(w_hh, whhT);
    cudaEventRecord(evP, 0);
    cudaStreamWaitEvent(s2, evP, 0);
    cudaStreamWaitEvent(s3, evP, 0);
    gemm128<<<dim3(3, 1), 256, 0, s2>>>(conv_w, wihT, wcomb, D, 3 * D);
    cudaEventRecord(evW0, s2);
    gemm128<<<dim3(3, 1), 256, 0, s3>>>(conv_w + (size_t)D * D, wihT,
                                        wcomb + (size_t)D * 3 * D, D, 3 * D);
    cudaEventRecord(evW1, s3);

    gather_kernel<<<(N * 32 + 255) / 256, 256>>>(node_ids, (const float4*)embed,
                                                 (float4*)h, (float4*)agg, N);

    int rowBlocks = (N + 127) / 128;   // 391

    for (int layer = 0; layer < 2; layer++) {
        // fork: gh = h @ w_hh^T on s2 (overlaps scatter+gi on main)
        cudaEventRecord(evF[layer], 0);
        cudaStreamWaitEvent(s2, evF[layer], 0);
        gemm128<<<dim3(3, rowBlocks), 256, 0, s2>>>(h, whhT, gh, N, 3 * D);
        cudaEventRecord(evJ[layer], s2);

        // main: agg[dst] += h[src]  (8 edges per warp)
        {
            int warps = (E + 7) / 8;
            int blocks = (warps + 7) / 8;
            scatter_kernel<<<blocks, 256>>>((const float4*)h, src, dst, agg, E);
        }

        // gi = agg @ Wcomb[layer]
        cudaStreamWaitEvent(0, layer == 0 ? evW0 : evW1, 0);
        gemm128<<<dim3(3, rowBlocks), 256>>>(agg, wcomb + (size_t)layer * D * 3 * D,
                                             gi, N, 3 * D);

        // join gh, fuse gates; zero agg for next layer's scatter
        cudaStreamWaitEvent(0, evJ[layer], 0);
        gru_kernel<<<(N * 32 + 255) / 256, 256>>>((const float4*)gi,
                                                  (const float4*)gh,
                                                  (const float4*)b_ih,
                                                  (const float4*)b_hh,
                                                  (float4*)h, (float4*)agg,
                                                  N * 32, layer == 0 ? 1 : 0);
    }

    pool_kernel<<<G, 512>>>(h, batch, out, N);
}

// round 15
// speedup vs baseline: 1.3480x; 1.1223x over previous
#include <cuda_runtime.h>
#include <cuda_bf16.h>
#include <cuda_fp16.h>
#include <math.h>
#include <stdint.h>

#define D 128
#define MAXN 50000

// ---------------- scratch ----------------
__device__ float  g_h[MAXN * D];
__device__ __half g_hh[MAXN * D];           // fp16 mirror of h (for scatter)
__device__ __half g_aggh[MAXN * D];         // fp16 scatter accumulator
__device__ float  g_gi[MAXN * 3 * D];
__device__ float  g_gh[MAXN * 3 * D];
__device__ float  g_wihT[D * 3 * D];        // [K=128][M=384]
__device__ float  g_whhT[D * 3 * D];
__device__ float  g_wcomb[2 * D * 3 * D];   // conv_w[l] @ w_ihT : [128][384] per layer

// ---------------- weight transpose: WT[k][m] = W[m][k], W is [384,128] ----------------
__global__ void transpose_kernel(const float* __restrict__ W, float* __restrict__ WT) {
    int idx = blockIdx.x * blockDim.x + threadIdx.x;
    if (idx >= 3 * D * D) return;
    int m = idx / D;
    int k = idx % D;
    WT[(size_t)k * (3 * D) + m] = W[idx];
}

// ---------------- FFMA2 (f32x2) register-blocked GEMM (proven R13) ----------------
// C[N x M] = A[N x 128] @ B[128 x M]; M multiple of 128.  AH != 0 -> A is fp16.
#define BK 16
template <int HALF_A>
__global__ __launch_bounds__(256, 2)
void gemm128(const void* __restrict__ Araw, const float* __restrict__ B,
             float* __restrict__ C, int N, int M) {
    __shared__ float As[BK][132];   // transposed As[k][m]
    __shared__ float Bs[BK][128];   // Bs[k][n]

    int tid = threadIdx.x;
    int block_row = blockIdx.y * 128;
    int block_col = blockIdx.x * 128;

    int aRow = tid >> 2;
    int aCol = (tid & 3) * 4;
    int bRow = tid >> 5;
    int bCol = (tid & 31) * 4;
    int tr = (tid >> 4) * 4;
    int tc = (tid & 15) * 4;

    uint64_t acc2[8][4];
#pragma unroll
    for (int i = 0; i < 8; i++)
#pragma unroll
        for (int j = 0; j < 4; j++) acc2[i][j] = 0ULL;

    for (int k0 = 0; k0 < 128; k0 += BK) {
#pragma unroll
        for (int p = 0; p < 2; p++) {
            int r = aRow + p * 64;
            int gr = block_row + r;
            float4 v = make_float4(0.f, 0.f, 0.f, 0.f);
            if (gr < N) {
                if (HALF_A) {
                    const __half* Ah = (const __half*)Araw;
                    uint2 u = *(const uint2*)(Ah + (size_t)gr * 128 + k0 + aCol);
                    float2 f01 = __half22float2(*reinterpret_cast<__half2*>(&u.x));
                    float2 f23 = __half22float2(*reinterpret_cast<__half2*>(&u.y));
                    v = make_float4(f01.x, f01.y, f23.x, f23.y);
                } else {
                    const float* Af = (const float*)Araw;
                    v = *(const float4*)(Af + (size_t)gr * 128 + k0 + aCol);
                }
            }
            As[aCol + 0][r] = v.x;
            As[aCol + 1][r] = v.y;
            As[aCol + 2][r] = v.z;
            As[aCol + 3][r] = v.w;
        }
#pragma unroll
        for (int p = 0; p < 2; p++) {
            int r = bRow + p * 8;
            float4 v = *(const float4*)(B + (size_t)(k0 + r) * M + block_col + bCol);
            *(float4*)&Bs[r][bCol] = v;
        }
        __syncthreads();

#pragma unroll
        for (int k = 0; k < BK; k++) {
            float4 m0 = *(const float4*)&As[k][tr];
            float4 m1 = *(const float4*)&As[k][tr + 64];
            const uint64_t* b0 = (const uint64_t*)&Bs[k][tc];
            const uint64_t* b1 = (const uint64_t*)&Bs[k][tc + 64];
            uint64_t bn[4] = {b0[0], b0[1], b1[0], b1[1]};
            float rm[8] = {m0.x, m0.y, m0.z, m0.w, m1.x, m1.y, m1.z, m1.w};
#pragma unroll
            for (int i = 0; i < 8; i++) {
                uint64_t rm2;
                uint32_t mu = __float_as_uint(rm[i]);
                asm("mov.b64 %0, {%1, %1};" : "=l"(rm2) : "r"(mu));
#pragma unroll
                for (int j = 0; j < 4; j++)
                    asm("fma.rn.f32x2 %0, %1, %2, %0;"
                        : "+l"(acc2[i][j]) : "l"(rm2), "l"(bn[j]));
            }
        }
        __syncthreads();
    }

#pragma unroll
    for (int ii = 0; ii < 2; ii++) {
#pragma unroll
        for (int i = 0; i < 4; i++) {
            int row = block_row + tr + ii * 64 + i;
            if (row >= N) continue;
#pragma unroll
            for (int jj = 0; jj < 2; jj++) {
                int col = block_col + tc + jj * 64;
                uint64_t p0 = acc2[ii * 4 + i][jj * 2 + 0];
                uint64_t p1 = acc2[ii * 4 + i][jj * 2 + 1];
                float4 r;
                r.x = __uint_as_float((uint32_t)p0);
                r.y = __uint_as_float((uint32_t)(p0 >> 32));
                r.z = __uint_as_float((uint32_t)p1);
                r.w = __uint_as_float((uint32_t)(p1 >> 32));
                *(float4*)&C[(size_t)row * M + col] = r;
            }
        }
    }
}

// ---------------- gather: h = embed[node_ids] (+fp16 mirror); zero agg_h ----------------
__global__ void gather_kernel(const int* __restrict__ node_ids,
                              const float4* __restrict__ embed4,
                              float4* __restrict__ h4,
                              uint2* __restrict__ hh2,
                              uint2* __restrict__ aggh2, int N) {
    int idx = blockIdx.x * blockDim.x + threadIdx.x;
    if (idx >= N * 32) return;
    int n = idx >> 5;
    int c = idx & 31;
    int id = node_ids[n];
    float4 v = embed4[(size_t)id * 32 + c];
    h4[(size_t)n * 32 + c] = v;
    __half2 a = __floats2half2_rn(v.x, v.y);
    __half2 b = __floats2half2_rn(v.z, v.w);
    uint2 u;
    u.x = *reinterpret_cast<uint32_t*>(&a);
    u.y = *reinterpret_cast<uint32_t*>(&b);
    hh2[idx] = u;
    aggh2[idx] = make_uint2(0u, 0u);
}

// ---------------- fp16 edge scatter: aggh[dst] += hh[src], 16 lanes/edge, 8 edges ILP ----------------
#define REDH4(P, V)                                                            \
    asm volatile("red.global.add.noftz.v4.f16x2 [%0], {%1, %2, %3, %4};"       \
                 :: "l"(P), "r"((V).x), "r"((V).y), "r"((V).z), "r"((V).w)     \
                 : "memory")

__global__ void scatter_kernel(const uint4* __restrict__ hh4,
                               const int* __restrict__ src,
                               const int* __restrict__ dst,
                               __half* __restrict__ aggh, int E) {
    int w = blockIdx.x * (blockDim.x >> 5) + (threadIdx.x >> 5);
    int lane = threadIdx.x & 31;
    int half16 = lane >> 4;        // 0/1: two edge groups per warp
    int l16 = lane & 15;           // 16 lanes x 16B = 256B row
    int e0 = w * 16 + half16 * 8;
    if (e0 >= E) return;
    if (e0 + 8 <= E) {
        int s[8], d[8];
#pragma unroll
        for (int i = 0; i < 8; i++) s[i] = __ldg(src + e0 + i);
#pragma unroll
        for (int i = 0; i < 8; i++) d[i] = __ldg(dst + e0 + i);
        uint4 v[8];
#pragma unroll
        for (int i = 0; i < 8; i++) v[i] = hh4[(size_t)s[i] * 16 + l16];
#pragma unroll
        for (int i = 0; i < 8; i++)
            REDH4(aggh + (size_t)d[i] * D + l16 * 8, v[i]);
    } else {
        for (int e = e0; e < E; e++) {
            int s = __ldg(src + e);
            int d = __ldg(dst + e);
            uint4 v = hh4[(size_t)s * 16 + l16];
            REDH4(aggh + (size_t)d * D + l16 * 8, v);
        }
    }
}

// ---------------- GRU gate fusion; writes h fp32 + fp16 mirror; optionally zero aggh ----------------
__global__ void gru_kernel(const float4* __restrict__ gi4,
                           const float4* __restrict__ gh4,
                           const float4* __restrict__ bih4,
                           const float4* __restrict__ bhh4,
                           float4* __restrict__ h4,
                           uint2* __restrict__ hh2,
                           uint2* __restrict__ aggh2,
                           int total4, int zero_agg) {
    int idx = blockIdx.x * blockDim.x + threadIdx.x;
    if (idx >= total4) return;
    int n = idx >> 5;
    int c = idx & 31;
    const float4* gin = gi4 + (size_t)n * 96;
    const float4* ghn = gh4 + (size_t)n * 96;
    float4 ir = gin[c], iz = gin[c + 32], in_ = gin[c + 64];
    float4 hr = ghn[c], hz = ghn[c + 32], hn = ghn[c + 64];
    float4 bir = bih4[c], biz = bih4[c + 32], bin = bih4[c + 64];
    float4 bhr = bhh4[c], bhz = bhh4[c + 32], bhn = bhh4[c + 64];
    float4 h = h4[idx];
    float4 o;
#define GRU1(X)                                                                 \
    {                                                                           \
        float r = 1.0f / (1.0f + __expf(-(ir.X + bir.X + hr.X + bhr.X)));       \
        float z = 1.0f / (1.0f + __expf(-(iz.X + biz.X + hz.X + bhz.X)));       \
        float nn = tanhf(in_.X + bin.X + r * (hn.X + bhn.X));                   \
        o.X = (1.0f - z) * nn + z * h.X;                                        \
    }
    GRU1(x) GRU1(y) GRU1(z) GRU1(w)
#undef GRU1
    h4[idx] = o;
    __half2 a = __floats2half2_rn(o.x, o.y);
    __half2 b = __floats2half2_rn(o.z, o.w);
    uint2 u;
    u.x = *reinterpret_cast<uint32_t*>(&a);
    u.y = *reinterpret_cast<uint32_t*>(&b);
    hh2[idx] = u;
    if (zero_agg) aggh2[idx] = make_uint2(0u, 0u);
}

// ---------------- per-graph mean pool (batch sorted) ----------------
__device__ __forceinline__ int lower_bound_dev(const int* a, int n, int key) {
    int lo = 0, hi = n;
    while (lo < hi) {
        int mid = (lo + hi) >> 1;
        if (a[mid] < key) lo = mid + 1; else hi = mid;
    }
    return lo;
}

__global__ void pool_kernel(const float* __restrict__ h,
                            const int* __restrict__ batch,
                            float* __restrict__ out, int N) {
    int g = blockIdx.x;
    int tid = threadIdx.x;
    int sub = tid >> 7;
    int d = tid & 127;
    __shared__ int s_lo, s_hi;
    __shared__ float sbuf[4][128];
    if (tid == 0) {
        s_lo = lower_bound_dev(batch, N, g);
        s_hi = lower_bound_dev(batch, N, g + 1);
    }
    __syncthreads();
    int lo = s_lo, hi = s_hi;
    float acc = 0.0f;
    for (int n = lo + sub; n < hi; n += 4)
        acc += h[(size_t)n * D + d];
    sbuf[sub][d] = acc;
    __syncthreads();
    if (sub == 0) {
        float total = sbuf[0][d] + sbuf[1][d] + sbuf[2][d] + sbuf[3][d];
        float cnt = (float)(hi - lo);
        out[(size_t)g * D + d] = total / fmaxf(cnt, 1.0f);
    }
}

// ---------------- launch ----------------
extern "C" void kernel_launch(void* const* d_in, const int* in_sizes, int n_in,
                              void* d_out, int out_size) {
    const int* node_ids = (const int*)d_in[0];
    const int* edge_index = (const int*)d_in[1];
    const int* batch = (const int*)d_in[2];
    const float* embed = (const float*)d_in[4];
    const float* conv_w = (const float*)d_in[5];   // [2][K=128][M=128]
    const float* w_ih = (const float*)d_in[6];
    const float* w_hh = (const float*)d_in[7];
    const float* b_ih = (const float*)d_in[8];
    const float* b_hh = (const float*)d_in[9];
    float* out = (float*)d_out;

    int N = in_sizes[0];
    int E = in_sizes[1] / 2;
    int G = out_size / D;
    const int* src = edge_index;
    const int* dst = edge_index + E;

    float *h, *gi, *gh, *wihT, *whhT, *wcomb;
    __half *hh, *aggh;
    cudaGetSymbolAddress((void**)&h, g_h);
    cudaGetSymbolAddress((void**)&hh, g_hh);
    cudaGetSymbolAddress((void**)&aggh, g_aggh);
    cudaGetSymbolAddress((void**)&gi, g_gi);
    cudaGetSymbolAddress((void**)&gh, g_gh);
    cudaGetSymbolAddress((void**)&wihT, g_wihT);
    cudaGetSymbolAddress((void**)&whhT, g_whhT);
    cudaGetSymbolAddress((void**)&wcomb, g_wcomb);

    static cudaStream_t s2 = nullptr, s3 = nullptr;
    static cudaEvent_t evF[2], evJ[2], evP, evW0, evW1;
    if (!s2) {
        cudaStreamCreateWithFlags(&s2, cudaStreamNonBlocking);
        cudaStreamCreateWithFlags(&s3, cudaStreamNonBlocking);
        for (int i = 0; i < 2; i++) {
            cudaEventCreateWithFlags(&evF[i], cudaEventDisableTiming);
            cudaEventCreateWithFlags(&evJ[i], cudaEventDisableTiming);
        }
        cudaEventCreateWithFlags(&evP, cudaEventDisableTiming);
        cudaEventCreateWithFlags(&evW0, cudaEventDisableTiming);
        cudaEventCreateWithFlags(&evW1, cudaEventDisableTiming);
    }

    // ---- prep: transposes, then both wcomb GEMMs concurrently on s2/s3 ----
    transpose_kernel<<<(3 * D * D + 255) / 256, 256>>>(w_ih, wihT);
    transpose_kernel<<<(3 * D * D + 255) / 256, 256>>>(w_hh, whhT);
    cudaEventRecord(evP, 0);
    cudaStreamWaitEvent(s2, evP, 0);
    cudaStreamWaitEvent(s3, evP, 0);
    gemm128<0><<<dim3(3, 1), 256, 0, s2>>>(conv_w, wihT, wcomb, D, 3 * D);
    cudaEventRecord(evW0, s2);
    gemm128<0><<<dim3(3, 1), 256, 0, s3>>>(conv_w + (size_t)D * D, wihT,
                                           wcomb + (size_t)D * 3 * D, D, 3 * D);
    cudaEventRecord(evW1, s3);

    gather_kernel<<<(N * 32 + 255) / 256, 256>>>(node_ids, (const float4*)embed,
                                                 (float4*)h, (uint2*)hh,
                                                 (uint2*)aggh, N);

    int rowBlocks = (N + 127) / 128;   // 391

    for (int layer = 0; layer < 2; layer++) {
        // fork: gh = h @ w_hh^T on s2 (overlaps scatter on main)
        cudaEventRecord(evF[layer], 0);
        cudaStreamWaitEvent(s2, evF[layer], 0);
        gemm128<0><<<dim3(3, rowBlocks), 256, 0, s2>>>(h, whhT, gh, N, 3 * D);
        cudaEventRecord(evJ[layer], s2);

        // main: aggh[dst] += hh[src]  (fp16, 16 edges per warp)
        {
            int warps = (E + 15) / 16;
            int blocks = (warps + 7) / 8;
            scatter_kernel<<<blocks, 256>>>((const uint4*)hh, src, dst, aggh, E);
        }

        // gi = aggh @ Wcomb[layer]  (fp16 A, converted in staging)
        cudaStreamWaitEvent(0, layer == 0 ? evW0 : evW1, 0);
        gemm128<1><<<dim3(3, rowBlocks), 256>>>(aggh,
                                                wcomb + (size_t)layer * D * 3 * D,
                                                gi, N, 3 * D);

        // join gh, fuse gates; zero aggh for next layer's scatter
        cudaStreamWaitEvent(0, evJ[layer], 0);
        gru_kernel<<<(N * 32 + 255) / 256, 256>>>((const float4*)gi,
                                                  (const float4*)gh,
                                                  (const float4*)b_ih,
                                                  (const float4*)b_hh,
                                                  (float4*)h, (uint2*)hh,
                                                  (uint2*)aggh,
                                                  N * 32, layer == 0 ? 1 : 0);
    }

    pool_kernel<<<G, 512>>>(h, batch, out, N);
}